// round 1
// baseline (speedup 1.0000x reference)
#include <cuda_runtime.h>
#include <stdint.h>

// Banded outer product: out[b,i,j] = s[b,i]*e[b,j] for 0 <= j-i <= 15, else 0.
// B=16, L=4096. Output 1.073 GB fp32 -> pure HBM-store-bound.
//
// Mapping: one block per output row (row = b*L + i), 256 threads,
// each thread writes 4 float4 chunks (1024 float4 per row).
// e[] is only loaded for chunks intersecting the band (<=5 chunks/row),
// keeping read traffic ~5 MB vs 1 GB writes.

#define LDIM 4096
#define BAND 15

__global__ __launch_bounds__(256, 8)
void band_outer_kernel(const float* __restrict__ s,
                       const float* __restrict__ e,
                       float* __restrict__ out)
{
    const int row = blockIdx.x;          // b*L + i
    const int i   = row & (LDIM - 1);
    const float sv = __ldg(&s[row]);
    const float* __restrict__ erow = e + (size_t)(row >> 12) * LDIM;

    float4* __restrict__ orow =
        reinterpret_cast<float4*>(out) + (size_t)row * (LDIM / 4);

    const int lo = i;            // first nonzero column
    const int hi = i + BAND;     // last nonzero column (may exceed L-1; j<L anyway)

#pragma unroll
    for (int k = 0; k < 4; ++k) {
        const int c4 = threadIdx.x + k * 256;   // float4 index in row
        const int j  = c4 << 2;                 // first column of this chunk
        float4 v = make_float4(0.f, 0.f, 0.f, 0.f);

        if (j + 3 >= lo && j <= hi) {
            // chunk intersects band: elementwise predicated loads
            int j0 = j;
            if (j0     >= lo && j0     <= hi) v.x = sv * __ldg(&erow[j0]);
            if (j0 + 1 >= lo && j0 + 1 <= hi) v.y = sv * __ldg(&erow[j0 + 1]);
            if (j0 + 2 >= lo && j0 + 2 <= hi) v.z = sv * __ldg(&erow[j0 + 2]);
            if (j0 + 3 >= lo && j0 + 3 <= hi) v.w = sv * __ldg(&erow[j0 + 3]);
        }
        // streaming store: output is write-once, keep it out of L2 residency
        __stcs(&orow[c4], v);
    }
}

extern "C" void kernel_launch(void* const* d_in, const int* in_sizes, int n_in,
                              void* d_out, int out_size)
{
    const float* s = (const float*)d_in[0];
    const float* e = (const float*)d_in[1];
    float* out = (float*)d_out;

    // 16 * 4096 rows, one block each
    band_outer_kernel<<<16 * LDIM, 256>>>(s, e, out);
}